// round 16
// baseline (speedup 1.0000x reference)
#include <cuda_runtime.h>
#include <math.h>

typedef unsigned long long ull;

#define NBC  6          // B*C
#define NBLK 384        // 64 blocks per bc; block = one 8x8x8 L2-cell region = one L5 cell

// Static __device__ scratch (allocation-free). Zero-init; finalize resets for replay.
__device__ double       g_acc[NBC][54];
__device__ unsigned int g_ctr;

// ---- packed f32x2 helpers (Blackwell 2xFP32; ptxas won't auto-emit) ----
__device__ __forceinline__ ull pk2(float lo, float hi) {
    ull r; asm("mov.b64 %0, {%1, %2};" : "=l"(r) : "f"(lo), "f"(hi)); return r;
}
__device__ __forceinline__ float2 upk2(ull v) {
    float2 f; asm("mov.b64 {%0, %1}, %2;" : "=f"(f.x), "=f"(f.y) : "l"(v)); return f;
}
__device__ __forceinline__ ull add2(ull a, ull b) {
    ull r; asm("add.rn.f32x2 %0, %1, %2;" : "=l"(r) : "l"(a), "l"(b)); return r;
}
__device__ __forceinline__ ull mul2(ull a, ull b) {
    ull r; asm("mul.rn.f32x2 %0, %1, %2;" : "=l"(r) : "l"(a), "l"(b)); return r;
}
__device__ __forceinline__ ull fma2(ull a, ull b, ull c) {
    ull r; asm("fma.rn.f32x2 %0, %1, %2, %3;" : "=l"(r) : "l"(a), "l"(b), "l"(c)); return r;
}
__device__ __forceinline__ float rcpa(float x) {
    float r; asm("rcp.approx.f32 %0, %1;" : "=f"(r) : "f"(x)); return r;
}
__device__ __forceinline__ float lg2a(float x) {
    float r; asm("lg2.approx.f32 %0, %1;" : "=f"(r) : "f"(x)); return r;
}

// cp.async 16B (L2-cached, streaming) + group ops
#define CP16(dst_u32, src_ptr) \
    asm volatile("cp.async.cg.shared.global [%0], [%1], 16;" \
                 :: "r"(dst_u32), "l"(src_ptr) : "memory")
#define CP_COMMIT() asm volatile("cp.async.commit_group;" ::: "memory")
#define CP_WAIT(n)  asm volatile("cp.async.wait_group %0;" :: "n"(n) : "memory")

__device__ __forceinline__ unsigned int s2u(const void* p) {
    return (unsigned int)__cvta_generic_to_shared(p);
}

// Packed pair accumulation, both values nonzero. 3 MUFU via rcp-of-product trick.
__device__ __forceinline__ void acc_pair_t(ull x, ull& S2, ull& S3, ull& S4,
                                           ull& S5, float& Sm1, float& Sm2,
                                           float& T2a, float& T2b) {
    float2 f = upk2(x);
    float r  = rcpa(f.x * f.y);             // MUFU.RCP
    float la = lg2a(f.x), lb = lg2a(f.y);   // 2x MUFU.LG2
    ull xx = mul2(x, x);
    S2 = add2(S2, xx);
    ull x3 = mul2(xx, x);
    S3 = add2(S3, x3);
    S4 = fma2(xx, xx, S4);
    S5 = fma2(x3, xx, S5);
    float2 fx = upk2(xx);
    Sm1 = fmaf(f.x + f.y, r, Sm1);
    Sm2 = fmaf(fx.x + fx.y, r * r, Sm2);
    T2a = fmaf(f.x, la, T2a);
    T2b = fmaf(f.y, lb, T2b);
}

// Scalar zero-skipping accumulation (rare slow path).
__device__ __forceinline__ void acc_one(float v, ull& S2, ull& S3, ull& S4,
                                        ull& S5, float& Sm1, float& Sm2, float& T2a,
                                        float& cnt) {
    if (v != 0.0f) {
        float inv = rcpa(v), lg = lg2a(v);
        float v2 = v * v, v3 = v2 * v;
        S2 = add2(S2, pk2(v2, 0.f));
        S3 = add2(S3, pk2(v3, 0.f));
        S4 = add2(S4, pk2(v2 * v2, 0.f));
        S5 = add2(S5, pk2(v3 * v2, 0.f));
        Sm1 += inv;
        Sm2 += inv * inv;
        T2a = fmaf(v, lg, T2a);
        cnt += 1.0f;
    }
}

// Stats WITHOUT stat0 (S1 redundant at L1..L4; derived from L5 sums).
__device__ __forceinline__ void acc_scalar8(float v, float* st) {
    if (v != 0.0f) {
        float inv = rcpa(v), lg = lg2a(v);
        float v2 = v * v, v3 = v2 * v;
        st[1] += v2;  st[2] += v3;
        st[3] += v2 * v2;  st[4] += v3 * v2;
        st[5] += inv;  st[6] += inv * inv;
        st[7] += v * lg;  st[8] += 1.0f;
    }
}

// Full 9-stat version (L5 only; one call per block).
__device__ __forceinline__ void acc_scalar9(float v, float* st) {
    if (v != 0.0f) {
        float inv = rcpa(v), lg = lg2a(v);
        float v2 = v * v, v3 = v2 * v;
        st[0] += v;
        st[1] += v2;  st[2] += v3;
        st[3] += v2 * v2;  st[4] += v3 * v2;
        st[5] += inv;  st[6] += inv * inv;
        st[7] += v * lg;  st[8] += 1.0f;
    }
}

__device__ __forceinline__ float wred32(float v) {
#pragma unroll
    for (int o = 16; o; o >>= 1) v += __shfl_down_sync(0xFFFFFFFFu, v, o);
    return v;
}

// L0 stats of one plane (4 rows x 4 floats = 16 voxels).
__device__ __forceinline__ void plane_stats(ulonglong2 A0, ulonglong2 A1,
                                            ulonglong2 A2, ulonglong2 A3,
                                            ull& S2, ull& S3, ull& S4, ull& S5,
                                            float& Sm1, float& Sm2, float& T2a,
                                            float& T2b, float& cnt) {
    ull pr = mul2(mul2(mul2(A0.x, A0.y), mul2(A1.x, A1.y)),
                  mul2(mul2(A2.x, A2.y), mul2(A3.x, A3.y)));
    float2 pf = upk2(pr);
    if (pf.x * pf.y != 0.0f) {
        acc_pair_t(A0.x, S2, S3, S4, S5, Sm1, Sm2, T2a, T2b);
        acc_pair_t(A0.y, S2, S3, S4, S5, Sm1, Sm2, T2a, T2b);
        acc_pair_t(A1.x, S2, S3, S4, S5, Sm1, Sm2, T2a, T2b);
        acc_pair_t(A1.y, S2, S3, S4, S5, Sm1, Sm2, T2a, T2b);
        acc_pair_t(A2.x, S2, S3, S4, S5, Sm1, Sm2, T2a, T2b);
        acc_pair_t(A2.y, S2, S3, S4, S5, Sm1, Sm2, T2a, T2b);
        acc_pair_t(A3.x, S2, S3, S4, S5, Sm1, Sm2, T2a, T2b);
        acc_pair_t(A3.y, S2, S3, S4, S5, Sm1, Sm2, T2a, T2b);
        cnt += 16.0f;
    } else {
        ull us[8] = {A0.x, A0.y, A1.x, A1.y, A2.x, A2.y, A3.x, A3.y};
#pragma unroll 4
        for (int j = 0; j < 8; j++) {
            float2 vv = upk2(us[j]);
            acc_one(vv.x, S2, S3, S4, S5, Sm1, Sm2, T2a, cnt);
            acc_one(vv.y, S2, S3, S4, S5, Sm1, Sm2, T2a, cnt);
        }
    }
}

// smem union: 48KB cp.async pipe, reused for reductions after the main loop.
union SmemU {
    char pipe[3][4][256][16];   // [stage][row][tid][16B] = 49152 bytes
    struct {
        float l2s[512];
        float l3s[64];
        float w0[8][9], w1[8][9], w2[8][9], w3[2][9];
        float bs[54];
        float accF[NBC][54];
        unsigned int flag;
    } red;
};

__global__ void __launch_bounds__(256, 4) fractal_kernel(const float* __restrict__ img,
                                                         const int* __restrict__ bounds,
                                                         float* __restrict__ out) {
    const int b   = blockIdx.x;
    const int tid = threadIdx.x;
    const int bc  = b >> 6, tile = b & 63;
    const int tw = tile & 3, th = (tile >> 2) & 3, td = tile >> 4;
    const int cw = tid & 7, ch = (tid >> 3) & 7, cd0 = tid >> 6;

    __shared__ SmemU sm;

    ull S2 = 0, S3 = 0, S4 = 0, S5 = 0;
    float Sm1 = 0.f, Sm2 = 0.f, T2a = 0.f, T2b = 0.f, cnt = 0.f;
    float st1[9];
#pragma unroll
    for (int j = 0; j < 9; j++) st1[j] = 0.f;
    float l2v0 = 0.f, l2v1 = 0.f;

    // thread's cell-0 base; plane p (0..7): + (p>>2)*2^18 + (p&3)*2^14 floats
    const float* base = img + ((size_t)bc << 21) + (((size_t)(td << 3) + cd0) << 16)
                      + (((th << 3) + ch) << 9) + (((tw << 3) + cw) << 2);

    const unsigned int slot = s2u(&sm.pipe[0][0][tid][0]);   // stage stride 16384, row 4096

#define ISSUE_PLANE(p, s)                                             \
    do {                                                              \
        const float* gp_ = base + (((p) >> 2) << 18) + (((p) & 3) << 14); \
        unsigned int d_ = slot + (s) * 16384;                         \
        CP16(d_,         gp_);                                        \
        CP16(d_ + 4096,  gp_ + 128);                                  \
        CP16(d_ + 8192,  gp_ + 256);                                  \
        CP16(d_ + 12288, gp_ + 384);                                  \
        CP_COMMIT();                                                  \
    } while (0)

#define CONSUME_PLANE(s, A0, A1, A2, A3)                                        \
    do {                                                                        \
        A0 = *reinterpret_cast<const ulonglong2*>(&sm.pipe[s][0][tid][0]);      \
        A1 = *reinterpret_cast<const ulonglong2*>(&sm.pipe[s][1][tid][0]);      \
        A2 = *reinterpret_cast<const ulonglong2*>(&sm.pipe[s][2][tid][0]);      \
        A3 = *reinterpret_cast<const ulonglong2*>(&sm.pipe[s][3][tid][0]);      \
    } while (0)

    ISSUE_PLANE(0, 0);
    ISSUE_PLANE(1, 1);
    ISSUE_PLANE(2, 2);

    ulonglong2 A0, A1, A2, A3;
    ull r0, r1, r2, r3;

#pragma unroll
    for (int pr = 0; pr < 4; pr++) {                     // dz-pairs
        const int pe = pr * 2, po = pe + 1;
        const int se = pe % 3, so = po % 3;

        // even plane
        if (pe <= 4) { CP_WAIT(2); } else { CP_WAIT(1); }   // pe=6: 1 pending after
        CONSUME_PLANE(se, A0, A1, A2, A3);
        plane_stats(A0, A1, A2, A3, S2, S3, S4, S5, Sm1, Sm2, T2a, T2b, cnt);
        r0 = add2(A0.x, A1.x); r1 = add2(A2.x, A3.x);
        r2 = add2(A0.y, A1.y); r3 = add2(A2.y, A3.y);
        if (pe + 3 <= 7) ISSUE_PLANE(pe + 3, (pe + 3) % 3);

        // odd plane
        if (po <= 4) { CP_WAIT(2); } else if (po == 5) { CP_WAIT(2); }
        else { CP_WAIT(0); }                              // po=7: drain
        CONSUME_PLANE(so, A0, A1, A2, A3);
        plane_stats(A0, A1, A2, A3, S2, S3, S4, S5, Sm1, Sm2, T2a, T2b, cnt);
        r0 = add2(r0, add2(A0.x, A1.x)); r1 = add2(r1, add2(A2.x, A3.x));
        r2 = add2(r2, add2(A0.y, A1.y)); r3 = add2(r3, add2(A2.y, A3.y));
        if (po + 3 <= 7) ISSUE_PLANE(po + 3, (po + 3) % 3);

        // 4 L1 octants of this dz-pair
        float2 f0 = upk2(r0), f1 = upk2(r1), f2 = upk2(r2), f3 = upk2(r3);
        float l00 = f0.x + f0.y, l01 = f1.x + f1.y;
        float l10 = f2.x + f2.y, l11 = f3.x + f3.y;
        acc_scalar8(l00, st1); acc_scalar8(l01, st1);
        acc_scalar8(l10, st1); acc_scalar8(l11, st1);
        float addv = (l00 + l01) + (l10 + l11);
        if (pr < 2) l2v0 += addv; else l2v1 += addv;
    }

    // L2 stats
    float st2[9];
#pragma unroll
    for (int j = 0; j < 9; j++) st2[j] = 0.f;
    acc_scalar8(l2v0, st2);
    acc_scalar8(l2v1, st2);

    __syncthreads();                  // pipe dead everywhere -> safe to reuse smem
    sm.red.l2s[tid]       = l2v0;
    sm.red.l2s[tid + 256] = l2v1;
    __syncthreads();

    // L3: 64 threads pool 2x2x2 from l2s (8x8x8)
    float st3[9];
    if (tid < 64) {
#pragma unroll
        for (int j = 0; j < 9; j++) st3[j] = 0.f;
        int jw = tid & 3, jh = (tid >> 2) & 3, jd = tid >> 4;
        int b3 = (jd << 7) | (jh << 4) | (jw << 1);
        float l3v = 0.f;
#pragma unroll
        for (int di = 0; di < 2; di++)
#pragma unroll
            for (int hi = 0; hi < 2; hi++)
#pragma unroll
                for (int wi = 0; wi < 2; wi++)
                    l3v += sm.red.l2s[b3 + (di << 6) + (hi << 3) + wi];
        acc_scalar8(l3v, st3);
        sm.red.l3s[tid] = l3v;
    }
    __syncthreads();

    // L4: 8 threads pool; L5 = block total (full 9 stats incl. S1 -> b)
    if (tid < 8) {
        int mw = tid & 1, mh = (tid >> 1) & 1, md = tid >> 2;
        int b4 = (md << 5) | (mh << 3) | (mw << 1);
        float l4v = 0.f;
#pragma unroll
        for (int di = 0; di < 2; di++)
#pragma unroll
            for (int hi = 0; hi < 2; hi++)
#pragma unroll
                for (int wi = 0; wi < 2; wi++)
                    l4v += sm.red.l3s[b4 + (di << 4) + (hi << 2) + wi];
        float st4[9];
#pragma unroll
        for (int j = 0; j < 9; j++) st4[j] = 0.f;
        acc_scalar8(l4v, st4);
        float l5v = l4v;
#pragma unroll
        for (int o = 4; o; o >>= 1) {
            l5v += __shfl_down_sync(0xFFu, l5v, o);
#pragma unroll
            for (int j = 0; j < 9; j++) st4[j] += __shfl_down_sync(0xFFu, st4[j], o);
        }
        if (tid == 0) {
#pragma unroll
            for (int j = 0; j < 9; j++) sm.red.bs[36 + j] = st4[j];   // L4
            float st5[9];
#pragma unroll
            for (int j = 0; j < 9; j++) st5[j] = 0.f;
            acc_scalar9(l5v, st5);                                     // incl. stat0=b
#pragma unroll
            for (int j = 0; j < 9; j++) sm.red.bs[45 + j] = st5[j];   // L5
        }
    }

    // warp staging: L0/L1/L2 across 8 warps, L3 across warps 0,1
    {
        float st0[9];
        float2 f;
        st0[0] = 0.f;
        f = upk2(S2); st0[1] = f.x + f.y;
        f = upk2(S3); st0[2] = f.x + f.y;
        f = upk2(S4); st0[3] = f.x + f.y;
        f = upk2(S5); st0[4] = f.x + f.y;
        st0[5] = Sm1; st0[6] = Sm2; st0[7] = T2a + T2b; st0[8] = cnt;
        int lane = tid & 31, warp = tid >> 5;
#pragma unroll
        for (int j = 0; j < 9; j++) {
            float a0 = wred32(st0[j]);
            float a1 = wred32(st1[j]);
            float a2 = wred32(st2[j]);
            if (lane == 0) { sm.red.w0[warp][j] = a0; sm.red.w1[warp][j] = a1;
                             sm.red.w2[warp][j] = a2; }
        }
        if (tid < 64) {
#pragma unroll
            for (int j = 0; j < 9; j++) {
                float a3 = wred32(st3[j]);
                if (lane == 0) sm.red.w3[warp][j] = a3;
            }
        }
    }
    __syncthreads();

    if (tid < 9) {
        float s = 0.f;
#pragma unroll
        for (int w = 0; w < 8; w++) s += sm.red.w0[w][tid];
        sm.red.bs[tid] = s;
    } else if (tid >= 32 && tid < 41) {
        int j = tid - 32;
        float s = 0.f;
#pragma unroll
        for (int w = 0; w < 8; w++) s += sm.red.w1[w][j];
        sm.red.bs[9 + j] = s;
    } else if (tid >= 64 && tid < 73) {
        int j = tid - 64;
        float s = 0.f;
#pragma unroll
        for (int w = 0; w < 8; w++) s += sm.red.w2[w][j];
        sm.red.bs[18 + j] = s;
    } else if (tid >= 96 && tid < 105) {
        int j = tid - 96;
        sm.red.bs[27 + j] = sm.red.w3[0][j] + sm.red.w3[1][j];
    }
    __syncthreads();

    // global accumulate (RED.ADD.F64, 54 spread addresses) + arrival
    if (tid < 54) {
        atomicAdd(&g_acc[bc][tid], (double)sm.red.bs[tid]);
        __threadfence();
    }
    __syncthreads();
    if (tid == 0) sm.red.flag = (atomicAdd(&g_ctr, 1u) == NBLK - 1) ? 1u : 0u;
    __syncthreads();
    if (!sm.red.flag) return;
    if (tid == 0) __threadfence();
    __syncthreads();

    // ================= FINALIZE (last block) =================
    for (int u = tid; u < NBC * 54; u += 256)
        sm.red.accF[u / 54][u % 54] = (float)g_acc[u / 54][u % 54];
    __syncthreads();
    // reset for next graph replay
    for (int u = tid; u < NBC * 54; u += 256) g_acc[u / 54][u % 54] = 0.0;
    if (tid == 0) g_ctr = 0;

    if (tid >= NBC * 8) return;
    int obc = tid >> 3;
    int k   = bounds[tid & 7];

    const float LN2 = 0.69314718055994531f;
    float bsum = sm.red.accF[obc][45];      // L5 S1 = total image sum
    float lnb  = logf(bsum);

    float sp = 0.0f, spq = 0.0f;
    for (int s = 0; s < 6; s++) {
        const float* a = &sm.red.accF[obc][s * 9];
        float pv;
        if (k == 1) {
            pv = (a[7] * LN2) / bsum - lnb;
        } else if (k == 0) {
            pv = logf(a[8]);
        } else {
            float S;
            switch (k) {
                case  2: S = a[1]; break;
                case  3: S = a[2]; break;
                case  4: S = a[3]; break;
                case  5: S = a[4]; break;
                case -1: S = a[5]; break;
                case -2: S = a[6]; break;
                default: S = __int_as_float(0x7FC00000); break;
            }
            pv = logf(S) - (float)k * lnb;
        }
        sp  += pv;
        spq += pv * ((float)s * LN2);
    }
    const float qs  = 15.0f * LN2;
    const float q2s = 55.0f * LN2 * LN2;
    const float den = 6.0f * q2s - qs * qs;
    float aa = (k == 1) ? 1.0f : 1.0f / (float)(k - 1);
    out[tid] = aa * (6.0f * spq - sp * qs) / den;
}

extern "C" void kernel_launch(void* const* d_in, const int* in_sizes, int n_in,
                              void* d_out, int out_size) {
    const float* img    = (const float*)d_in[0];
    const int*   bounds = (const int*)d_in[1];
    float*       out    = (float*)d_out;

    fractal_kernel<<<NBLK, 256>>>(img, bounds, out);
}

// round 17
// speedup vs baseline: 1.5644x; 1.5644x over previous
#include <cuda_runtime.h>
#include <math.h>

typedef unsigned long long ull;

#define NBC  6          // B*C
#define NBLK 384        // 64 blocks per bc; block = one 8x8x8 L2-cell region = one L5 cell

// Static __device__ scratch (allocation-free). Zero-init; finalize resets for replay.
__device__ double       g_acc[NBC][54];
__device__ unsigned int g_ctr;

// ---- packed f32x2 helpers (Blackwell 2xFP32; ptxas won't auto-emit) ----
__device__ __forceinline__ ull pk2(float lo, float hi) {
    ull r; asm("mov.b64 %0, {%1, %2};" : "=l"(r) : "f"(lo), "f"(hi)); return r;
}
__device__ __forceinline__ float2 upk2(ull v) {
    float2 f; asm("mov.b64 {%0, %1}, %2;" : "=f"(f.x), "=f"(f.y) : "l"(v)); return f;
}
__device__ __forceinline__ ull add2(ull a, ull b) {
    ull r; asm("add.rn.f32x2 %0, %1, %2;" : "=l"(r) : "l"(a), "l"(b)); return r;
}
__device__ __forceinline__ ull mul2(ull a, ull b) {
    ull r; asm("mul.rn.f32x2 %0, %1, %2;" : "=l"(r) : "l"(a), "l"(b)); return r;
}
__device__ __forceinline__ ull fma2(ull a, ull b, ull c) {
    ull r; asm("fma.rn.f32x2 %0, %1, %2, %3;" : "=l"(r) : "l"(a), "l"(b), "l"(c)); return r;
}
__device__ __forceinline__ float rcpa(float x) {
    float r; asm("rcp.approx.f32 %0, %1;" : "=f"(r) : "f"(x)); return r;
}
__device__ __forceinline__ float lg2a(float x) {
    float r; asm("lg2.approx.f32 %0, %1;" : "=f"(r) : "f"(x)); return r;
}
__device__ __forceinline__ ulonglong2 ld2(const float* p) {
    return *reinterpret_cast<const ulonglong2*>(p);
}

// Packed pair accumulation, both values nonzero. 3 MUFU via rcp-of-product trick.
__device__ __forceinline__ void acc_pair_t(ull x, ull& S2, ull& S3, ull& S4,
                                           ull& S5, float& Sm1, float& Sm2,
                                           float& T2a, float& T2b) {
    float2 f = upk2(x);
    float r  = rcpa(f.x * f.y);             // MUFU.RCP
    float la = lg2a(f.x), lb = lg2a(f.y);   // 2x MUFU.LG2
    ull xx = mul2(x, x);
    S2 = add2(S2, xx);
    ull x3 = mul2(xx, x);
    S3 = add2(S3, x3);
    S4 = fma2(xx, xx, S4);
    S5 = fma2(x3, xx, S5);
    float2 fx = upk2(xx);
    Sm1 = fmaf(f.x + f.y, r, Sm1);
    Sm2 = fmaf(fx.x + fx.y, r * r, Sm2);
    T2a = fmaf(f.x, la, T2a);
    T2b = fmaf(f.y, lb, T2b);
}

// Scalar zero-skipping accumulation (rare slow path).
__device__ __forceinline__ void acc_one(float v, ull& S2, ull& S3, ull& S4,
                                        ull& S5, float& Sm1, float& Sm2, float& T2a,
                                        float& cnt) {
    if (v != 0.0f) {
        float inv = rcpa(v), lg = lg2a(v);
        float v2 = v * v, v3 = v2 * v;
        S2 = add2(S2, pk2(v2, 0.f));
        S3 = add2(S3, pk2(v3, 0.f));
        S4 = add2(S4, pk2(v2 * v2, 0.f));
        S5 = add2(S5, pk2(v3 * v2, 0.f));
        Sm1 += inv;
        Sm2 += inv * inv;
        T2a = fmaf(v, lg, T2a);
        cnt += 1.0f;
    }
}

// Stats WITHOUT stat0 (S1 redundant at L1..L4; derived from L5 sums).
__device__ __forceinline__ void acc_scalar8(float v, float* st) {
    if (v != 0.0f) {
        float inv = rcpa(v), lg = lg2a(v);
        float v2 = v * v, v3 = v2 * v;
        st[1] += v2;  st[2] += v3;
        st[3] += v2 * v2;  st[4] += v3 * v2;
        st[5] += inv;  st[6] += inv * inv;
        st[7] += v * lg;  st[8] += 1.0f;
    }
}

// Full 9-stat version (L5 only; one call per block).
__device__ __forceinline__ void acc_scalar9(float v, float* st) {
    if (v != 0.0f) {
        float inv = rcpa(v), lg = lg2a(v);
        float v2 = v * v, v3 = v2 * v;
        st[0] += v;
        st[1] += v2;  st[2] += v3;
        st[3] += v2 * v2;  st[4] += v3 * v2;
        st[5] += inv;  st[6] += inv * inv;
        st[7] += v * lg;  st[8] += 1.0f;
    }
}

__device__ __forceinline__ float wred32(float v) {
#pragma unroll
    for (int o = 16; o; o >>= 1) v += __shfl_down_sync(0xFFFFFFFFu, v, o);
    return v;
}

// L0 stats of one plane (4 rows x 4 floats = 16 voxels).
__device__ __forceinline__ void plane_stats(ulonglong2 A0, ulonglong2 A1,
                                            ulonglong2 A2, ulonglong2 A3,
                                            ull& S2, ull& S3, ull& S4, ull& S5,
                                            float& Sm1, float& Sm2, float& T2a,
                                            float& T2b, float& cnt) {
    ull pr = mul2(mul2(mul2(A0.x, A0.y), mul2(A1.x, A1.y)),
                  mul2(mul2(A2.x, A2.y), mul2(A3.x, A3.y)));
    float2 pf = upk2(pr);
    if (pf.x * pf.y != 0.0f) {
        acc_pair_t(A0.x, S2, S3, S4, S5, Sm1, Sm2, T2a, T2b);
        acc_pair_t(A0.y, S2, S3, S4, S5, Sm1, Sm2, T2a, T2b);
        acc_pair_t(A1.x, S2, S3, S4, S5, Sm1, Sm2, T2a, T2b);
        acc_pair_t(A1.y, S2, S3, S4, S5, Sm1, Sm2, T2a, T2b);
        acc_pair_t(A2.x, S2, S3, S4, S5, Sm1, Sm2, T2a, T2b);
        acc_pair_t(A2.y, S2, S3, S4, S5, Sm1, Sm2, T2a, T2b);
        acc_pair_t(A3.x, S2, S3, S4, S5, Sm1, Sm2, T2a, T2b);
        acc_pair_t(A3.y, S2, S3, S4, S5, Sm1, Sm2, T2a, T2b);
        cnt += 16.0f;
    } else {
        ull us[8] = {A0.x, A0.y, A1.x, A1.y, A2.x, A2.y, A3.x, A3.y};
#pragma unroll 4
        for (int j = 0; j < 8; j++) {
            float2 vv = upk2(us[j]);
            acc_one(vv.x, S2, S3, S4, S5, Sm1, Sm2, T2a, cnt);
            acc_one(vv.y, S2, S3, S4, S5, Sm1, Sm2, T2a, cnt);
        }
    }
}

// smem union: 16KB L1-value buffer (loop), reused for reductions after it.
union SmemU {
    float l1buf[16][256];       // 16384 bytes; [octant][tid], thread-private access
    struct {
        float l2s[512];
        float l3s[64];
        float w0[8][9], w1[8][9], w2[8][9], w3[2][9];
        float bs[54];
        float accF[NBC][54];
        unsigned int flag;
    } red;
};

__global__ void __launch_bounds__(256, 4) fractal_kernel(const float* __restrict__ img,
                                                         const int* __restrict__ bounds,
                                                         float* __restrict__ out) {
    const int b   = blockIdx.x;
    const int tid = threadIdx.x;
    const int bc  = b >> 6, tile = b & 63;
    const int tw = tile & 3, th = (tile >> 2) & 3, td = tile >> 4;
    const int cw = tid & 7, ch = (tid >> 3) & 7, cd0 = tid >> 6;

    __shared__ SmemU sm;

    ull S2 = 0, S3 = 0, S4 = 0, S5 = 0;
    float Sm1 = 0.f, Sm2 = 0.f, T2a = 0.f, T2b = 0.f, cnt = 0.f;
    float l2v0 = 0.f, l2v1 = 0.f;

    // thread's cell-0 base; dz-pair pr (0..3): cell pr>>1, pair pr&1.
    const float* base = img + ((size_t)bc << 21) + (((size_t)(td << 3) + cd0) << 16)
                      + (((th << 3) + ch) << 9) + (((tw << 3) + cw) << 2);

#pragma unroll
    for (int pr = 0; pr < 4; pr++) {
        const float* gp = base + ((pr >> 1) << 18) + ((pr & 1) << 15);
        ull r0, r1, r2, r3;

        // even plane
        ulonglong2 A0 = ld2(gp), A1 = ld2(gp + 128), A2 = ld2(gp + 256), A3 = ld2(gp + 384);
        plane_stats(A0, A1, A2, A3, S2, S3, S4, S5, Sm1, Sm2, T2a, T2b, cnt);
        r0 = add2(A0.x, A1.x); r1 = add2(A2.x, A3.x);
        r2 = add2(A0.y, A1.y); r3 = add2(A2.y, A3.y);

        // odd plane
        const float* go = gp + 16384;
        A0 = ld2(go); A1 = ld2(go + 128); A2 = ld2(go + 256); A3 = ld2(go + 384);
        plane_stats(A0, A1, A2, A3, S2, S3, S4, S5, Sm1, Sm2, T2a, T2b, cnt);
        r0 = add2(r0, add2(A0.x, A1.x)); r1 = add2(r1, add2(A2.x, A3.x));
        r2 = add2(r2, add2(A0.y, A1.y)); r3 = add2(r3, add2(A2.y, A3.y));

        // 4 L1 octants of this dz-pair -> smem (stats deferred), accumulate L2
        float2 f0 = upk2(r0), f1 = upk2(r1), f2 = upk2(r2), f3 = upk2(r3);
        float l00 = f0.x + f0.y, l01 = f1.x + f1.y;
        float l10 = f2.x + f2.y, l11 = f3.x + f3.y;
        sm.l1buf[pr * 4 + 0][tid] = l00;
        sm.l1buf[pr * 4 + 1][tid] = l01;
        sm.l1buf[pr * 4 + 2][tid] = l10;
        sm.l1buf[pr * 4 + 3][tid] = l11;
        float addv = (l00 + l01) + (l10 + l11);
        if (pr < 2) l2v0 += addv; else l2v1 += addv;
    }

    // deferred L1 stats (reads only this thread's own smem slots; no sync needed)
    float st1[9];
#pragma unroll
    for (int j = 0; j < 9; j++) st1[j] = 0.f;
#pragma unroll
    for (int i = 0; i < 16; i++) acc_scalar8(sm.l1buf[i][tid], st1);

    // L2 stats
    float st2[9];
#pragma unroll
    for (int j = 0; j < 9; j++) st2[j] = 0.f;
    acc_scalar8(l2v0, st2);
    acc_scalar8(l2v1, st2);

    __syncthreads();                  // all threads done with l1buf -> reuse smem
    sm.red.l2s[tid]       = l2v0;
    sm.red.l2s[tid + 256] = l2v1;
    __syncthreads();

    // L3: 64 threads pool 2x2x2 from l2s (8x8x8)
    float st3[9];
    if (tid < 64) {
#pragma unroll
        for (int j = 0; j < 9; j++) st3[j] = 0.f;
        int jw = tid & 3, jh = (tid >> 2) & 3, jd = tid >> 4;
        int b3 = (jd << 7) | (jh << 4) | (jw << 1);
        float l3v = 0.f;
#pragma unroll
        for (int di = 0; di < 2; di++)
#pragma unroll
            for (int hi = 0; hi < 2; hi++)
#pragma unroll
                for (int wi = 0; wi < 2; wi++)
                    l3v += sm.red.l2s[b3 + (di << 6) + (hi << 3) + wi];
        acc_scalar8(l3v, st3);
        sm.red.l3s[tid] = l3v;
    }
    __syncthreads();

    // L4: 8 threads pool; L5 = block total (full 9 stats incl. S1 -> b)
    if (tid < 8) {
        int mw = tid & 1, mh = (tid >> 1) & 1, md = tid >> 2;
        int b4 = (md << 5) | (mh << 3) | (mw << 1);
        float l4v = 0.f;
#pragma unroll
        for (int di = 0; di < 2; di++)
#pragma unroll
            for (int hi = 0; hi < 2; hi++)
#pragma unroll
                for (int wi = 0; wi < 2; wi++)
                    l4v += sm.red.l3s[b4 + (di << 4) + (hi << 2) + wi];
        float st4[9];
#pragma unroll
        for (int j = 0; j < 9; j++) st4[j] = 0.f;
        acc_scalar8(l4v, st4);
        float l5v = l4v;
#pragma unroll
        for (int o = 4; o; o >>= 1) {
            l5v += __shfl_down_sync(0xFFu, l5v, o);
#pragma unroll
            for (int j = 0; j < 9; j++) st4[j] += __shfl_down_sync(0xFFu, st4[j], o);
        }
        if (tid == 0) {
#pragma unroll
            for (int j = 0; j < 9; j++) sm.red.bs[36 + j] = st4[j];   // L4
            float st5[9];
#pragma unroll
            for (int j = 0; j < 9; j++) st5[j] = 0.f;
            acc_scalar9(l5v, st5);                                     // incl. stat0=b
#pragma unroll
            for (int j = 0; j < 9; j++) sm.red.bs[45 + j] = st5[j];   // L5
        }
    }

    // warp staging: L0/L1/L2 across 8 warps, L3 across warps 0,1
    {
        float st0[9];
        float2 f;
        st0[0] = 0.f;
        f = upk2(S2); st0[1] = f.x + f.y;
        f = upk2(S3); st0[2] = f.x + f.y;
        f = upk2(S4); st0[3] = f.x + f.y;
        f = upk2(S5); st0[4] = f.x + f.y;
        st0[5] = Sm1; st0[6] = Sm2; st0[7] = T2a + T2b; st0[8] = cnt;
        int lane = tid & 31, warp = tid >> 5;
#pragma unroll
        for (int j = 0; j < 9; j++) {
            float a0 = wred32(st0[j]);
            float a1 = wred32(st1[j]);
            float a2 = wred32(st2[j]);
            if (lane == 0) { sm.red.w0[warp][j] = a0; sm.red.w1[warp][j] = a1;
                             sm.red.w2[warp][j] = a2; }
        }
        if (tid < 64) {
#pragma unroll
            for (int j = 0; j < 9; j++) {
                float a3 = wred32(st3[j]);
                if (lane == 0) sm.red.w3[warp][j] = a3;
            }
        }
    }
    __syncthreads();

    if (tid < 9) {
        float s = 0.f;
#pragma unroll
        for (int w = 0; w < 8; w++) s += sm.red.w0[w][tid];
        sm.red.bs[tid] = s;
    } else if (tid >= 32 && tid < 41) {
        int j = tid - 32;
        float s = 0.f;
#pragma unroll
        for (int w = 0; w < 8; w++) s += sm.red.w1[w][j];
        sm.red.bs[9 + j] = s;
    } else if (tid >= 64 && tid < 73) {
        int j = tid - 64;
        float s = 0.f;
#pragma unroll
        for (int w = 0; w < 8; w++) s += sm.red.w2[w][j];
        sm.red.bs[18 + j] = s;
    } else if (tid >= 96 && tid < 105) {
        int j = tid - 96;
        sm.red.bs[27 + j] = sm.red.w3[0][j] + sm.red.w3[1][j];
    }
    __syncthreads();

    // global accumulate (RED.ADD.F64, 54 spread addresses) + arrival
    if (tid < 54) {
        atomicAdd(&g_acc[bc][tid], (double)sm.red.bs[tid]);
        __threadfence();
    }
    __syncthreads();
    if (tid == 0) sm.red.flag = (atomicAdd(&g_ctr, 1u) == NBLK - 1) ? 1u : 0u;
    __syncthreads();
    if (!sm.red.flag) return;
    if (tid == 0) __threadfence();
    __syncthreads();

    // ================= FINALIZE (last block) =================
    for (int u = tid; u < NBC * 54; u += 256)
        sm.red.accF[u / 54][u % 54] = (float)g_acc[u / 54][u % 54];
    __syncthreads();
    // reset for next graph replay
    for (int u = tid; u < NBC * 54; u += 256) g_acc[u / 54][u % 54] = 0.0;
    if (tid == 0) g_ctr = 0;

    if (tid >= NBC * 8) return;
    int obc = tid >> 3;
    int k   = bounds[tid & 7];

    const float LN2 = 0.69314718055994531f;
    float bsum = sm.red.accF[obc][45];      // L5 S1 = total image sum
    float lnb  = logf(bsum);

    float sp = 0.0f, spq = 0.0f;
    for (int s = 0; s < 6; s++) {
        const float* a = &sm.red.accF[obc][s * 9];
        float pv;
        if (k == 1) {
            pv = (a[7] * LN2) / bsum - lnb;
        } else if (k == 0) {
            pv = logf(a[8]);
        } else {
            float S;
            switch (k) {
                case  2: S = a[1]; break;
                case  3: S = a[2]; break;
                case  4: S = a[3]; break;
                case  5: S = a[4]; break;
                case -1: S = a[5]; break;
                case -2: S = a[6]; break;
                default: S = __int_as_float(0x7FC00000); break;
            }
            pv = logf(S) - (float)k * lnb;
        }
        sp  += pv;
        spq += pv * ((float)s * LN2);
    }
    const float qs  = 15.0f * LN2;
    const float q2s = 55.0f * LN2 * LN2;
    const float den = 6.0f * q2s - qs * qs;
    float aa = (k == 1) ? 1.0f : 1.0f / (float)(k - 1);
    out[tid] = aa * (6.0f * spq - sp * qs) / den;
}

extern "C" void kernel_launch(void* const* d_in, const int* in_sizes, int n_in,
                              void* d_out, int out_size) {
    const float* img    = (const float*)d_in[0];
    const int*   bounds = (const int*)d_in[1];
    float*       out    = (float*)d_out;

    fractal_kernel<<<NBLK, 256>>>(img, bounds, out);
}